// round 6
// baseline (speedup 1.0000x reference)
#include <cuda_runtime.h>
#include <cuda_bf16.h>
#include <cstdint>

// ============================================================================
// output = 100/512 * (#pos edges with logit<=0.5 + #neg edges with logit>0.5)
// logit = W2 . relu(W1 . relu(x_i*x_j) + b1) + b2.
// (mean of segment sums == total/NUM_GRAPHS, so `batch` is irrelevant;
//  each misclassified edge contributes exactly 100 to the total loss.)
//
// Tensor path: mma.sync.m16n8k16 bf16 (plain sm_103 PTX target — tcgen05 is
// 'a'-suffix-only and the harness PTX pass targets sm_103).
// ============================================================================

#define NUM_GRAPHS 512
#define HDIM 160
#define TILE_M 128
#define NTHREADS 256
#define ROWB 336              // padded row pitch (bytes) for conflict-free ldmatrix

// ---- scratch (no cudaMalloc allowed) ----
__device__ __nv_bfloat16 g_xbf[16000000];   // 100000 x 160 bf16 = 32MB
__device__ int g_count;

// ---- dynamic SMEM layout (bytes) ----
#define OFF_SI   0                          // int[128]
#define OFF_SJ   512                        // int[128]
#define OFF_BW   1024                       // float2[160] {b1, w2}  (1280B)
#define OFF_A    2304                       // 128 rows x 336B = 43008
#define OFF_B    45312                      // 160 rows x 336B = 53760
#define SMEM_TOTAL 99328

__device__ __forceinline__ uint32_t smem_u32(const void* p) {
    uint32_t a;
    asm("{ .reg .u64 t; cvta.to.shared.u64 t, %1; cvt.u32.u64 %0, t; }"
        : "=r"(a) : "l"(p));
    return a;
}

__device__ __forceinline__ void ldsm_x4(uint32_t* r, uint32_t addr) {
    asm volatile("ldmatrix.sync.aligned.m8n8.x4.shared.b16 {%0,%1,%2,%3}, [%4];"
                 : "=r"(r[0]), "=r"(r[1]), "=r"(r[2]), "=r"(r[3]) : "r"(addr));
}

__device__ __forceinline__ void mma16816(float* d, const uint32_t* a,
                                         const uint32_t* b) {
    asm volatile(
        "mma.sync.aligned.m16n8k16.row.col.f32.bf16.bf16.f32 "
        "{%0,%1,%2,%3}, {%4,%5,%6,%7}, {%8,%9}, {%0,%1,%2,%3};"
        : "+f"(d[0]), "+f"(d[1]), "+f"(d[2]), "+f"(d[3])
        : "r"(a[0]), "r"(a[1]), "r"(a[2]), "r"(a[3]), "r"(b[0]), "r"(b[1]));
}

// bf16x2 multiply + relu, packed
__device__ __forceinline__ uint32_t bfmr(uint32_t a, uint32_t b) {
    __nv_bfloat162 x = *reinterpret_cast<__nv_bfloat162*>(&a);
    __nv_bfloat162 y = *reinterpret_cast<__nv_bfloat162*>(&b);
    __nv_bfloat162 z = __hmul2(x, y);
    const __nv_bfloat162 zero = __float2bfloat162_rn(0.0f);
    z = __hmax2(z, zero);
    return *reinterpret_cast<uint32_t*>(&z);
}

// ============================================================================
// Kernel 0: convert x -> bf16 scratch, zero counter
// ============================================================================
__global__ void cvt_kernel(const float* __restrict__ x, int n4) {
    if (blockIdx.x == 0 && threadIdx.x == 0) g_count = 0;
    int stride = gridDim.x * blockDim.x;
    uint2* out = reinterpret_cast<uint2*>(g_xbf);
    const float4* in = reinterpret_cast<const float4*>(x);
    for (int i = blockIdx.x * blockDim.x + threadIdx.x; i < n4; i += stride) {
        float4 v = in[i];
        __nv_bfloat162 p0 = __floats2bfloat162_rn(v.x, v.y);
        __nv_bfloat162 p1 = __floats2bfloat162_rn(v.z, v.w);
        uint2 o;
        o.x = *reinterpret_cast<uint32_t*>(&p0);
        o.y = *reinterpret_cast<uint32_t*>(&p1);
        out[i] = o;
    }
}

// ============================================================================
// Kernel 1: persistent fused edge-MLP + misclassification count
// ============================================================================
__global__ void __launch_bounds__(NTHREADS, 1)
gae_main_kernel(const int* __restrict__ pos, const int* __restrict__ neg,
                const float* __restrict__ W1, const float* __restrict__ b1,
                const float* __restrict__ W2, const float* __restrict__ b2,
                int Ep, int En) {
    extern __shared__ char smem[];
    const uint32_t sb = smem_u32(smem);
    const int tid = threadIdx.x;
    const int wid = tid >> 5;
    const int lid = tid & 31;
    const int Etot = Ep + En;
    const int ntiles = (Etot + TILE_M - 1) / TILE_M;

    // --- load W1 -> SMEM B [160 rows x 336B pitch], f32 -> bf16 ---
    {
        const float4* w1v = reinterpret_cast<const float4*>(W1);
        #pragma unroll 5
        for (int it = 0; it < 25; ++it) {
            int idx = it * NTHREADS + tid;        // 0..6399
            int n  = idx / 40;                    // N row 0..159
            int kc = idx - n * 40;                // float4 chunk 0..39
            float4 w = w1v[idx];
            __nv_bfloat162 p0 = __floats2bfloat162_rn(w.x, w.y);
            __nv_bfloat162 p1 = __floats2bfloat162_rn(w.z, w.w);
            uint2 v;
            v.x = *reinterpret_cast<uint32_t*>(&p0);
            v.y = *reinterpret_cast<uint32_t*>(&p1);
            *reinterpret_cast<uint2*>(smem + OFF_B + n * ROWB + kc * 8) = v;
        }
    }
    if (tid < HDIM) {
        reinterpret_cast<float2*>(smem + OFF_BW)[tid] = make_float2(b1[tid], W2[tid]);
    }
    __syncthreads();

    int* si = reinterpret_cast<int*>(smem + OFF_SI);
    int* sj = reinterpret_cast<int*>(smem + OFF_SJ);
    const float2* sbw = reinterpret_cast<const float2*>(smem + OFF_BW);
    const uint4* xrows = reinterpret_cast<const uint4*>(g_xbf);  // 20 uint4/row
    const float b2v = b2[0];

    // per-thread ldmatrix bases
    // A .x4 at k-step s: matrix m=lid>>3: rows (m&1)*8, cols (m>>1)*8
    const uint32_t aBase = sb + OFF_A
        + (uint32_t)((wid * 16 + ((lid >> 3) & 1) * 8 + (lid & 7)) * ROWB)
        + (uint32_t)((lid >> 4) * 16);            // (m>>1)*8 cols * 2B
    // B .x4 at (j, s2): matrix m=lid>>3 -> k offset m*8; row n = j*8+(lid&7)
    const uint32_t bBase = sb + OFF_B
        + (uint32_t)((lid & 7) * ROWB) + (uint32_t)((lid >> 3) * 16);

    int cnt = 0;

    for (int tile = blockIdx.x; tile < ntiles; tile += gridDim.x) {
        // ---- edge endpoints ----
        if (tid < TILE_M) {
            int g = tile * TILE_M + tid;
            int i0 = 0, j0 = 0;
            if (g < Etot) {
                if (g < Ep) { i0 = pos[g];      j0 = pos[g + Ep]; }
                else        { int q = g - Ep; i0 = neg[q]; j0 = neg[q + En]; }
            }
            si[tid] = i0;
            sj[tid] = j0;
        }
        __syncthreads();

        // ---- gather x_i, x_j; relu(prod) -> A tile (bf16, padded rows) ----
        #pragma unroll
        for (int it = 0; it < 10; ++it) {
            int item = it * NTHREADS + tid;       // 0..2559
            int e = item / 20;
            int c = item - e * 20;
            uint4 va = xrows[(size_t)si[e] * 20 + c];
            uint4 vb = xrows[(size_t)sj[e] * 20 + c];
            uint4 r;
            r.x = bfmr(va.x, vb.x);
            r.y = bfmr(va.y, vb.y);
            r.z = bfmr(va.z, vb.z);
            r.w = bfmr(va.w, vb.w);
            *reinterpret_cast<uint4*>(smem + OFF_A + e * ROWB + c * 16) = r;
        }
        __syncthreads();

        // ---- load A fragments for this warp's 16 rows (all K) ----
        uint32_t afrag[10][4];
        #pragma unroll
        for (int s = 0; s < 10; ++s) ldsm_x4(afrag[s], aBase + s * 32);

        // ---- D = A @ W1^T, fused epilogue per 8-col chunk ----
        float accLo = 0.0f, accHi = 0.0f;
        #pragma unroll
        for (int j = 0; j < 20; ++j) {
            float d[4] = {0.0f, 0.0f, 0.0f, 0.0f};
            uint32_t bj = bBase + (uint32_t)(j * 8 * ROWB);
            #pragma unroll
            for (int s2 = 0; s2 < 5; ++s2) {
                uint32_t br[4];
                ldsm_x4(br, bj + s2 * 64);        // k-steps 2*s2, 2*s2+1
                mma16816(d, afrag[s2 * 2],     br);
                mma16816(d, afrag[s2 * 2 + 1], br + 2);
            }
            int n0 = j * 8 + (lid & 3) * 2;
            float2 bw0 = sbw[n0];
            float2 bw1 = sbw[n0 + 1];
            accLo += fmaxf(d[0] + bw0.x, 0.0f) * bw0.y
                   + fmaxf(d[1] + bw1.x, 0.0f) * bw1.y;
            accHi += fmaxf(d[2] + bw0.x, 0.0f) * bw0.y
                   + fmaxf(d[3] + bw1.x, 0.0f) * bw1.y;
        }

        // ---- reduce across the 4 lanes of each row group ----
        accLo += __shfl_xor_sync(0xFFFFFFFFu, accLo, 1);
        accLo += __shfl_xor_sync(0xFFFFFFFFu, accLo, 2);
        accHi += __shfl_xor_sync(0xFFFFFFFFu, accHi, 1);
        accHi += __shfl_xor_sync(0xFFFFFFFFu, accHi, 2);

        if ((lid & 3) == 0) {
            int rbase = tile * TILE_M + wid * 16 + (lid >> 2);
            // row rbase (accLo)
            if (rbase < Etot) {
                bool pred = (accLo + b2v) > 0.5f;
                if (pred != (rbase < Ep)) cnt++;
            }
            int r2 = rbase + 8;
            if (r2 < Etot) {
                bool pred = (accHi + b2v) > 0.5f;
                if (pred != (r2 < Ep)) cnt++;
            }
        }
        __syncthreads();   // A smem / si consumed before next tile overwrites
    }

    // ---- reduce counts ----
    #pragma unroll
    for (int o = 16; o; o >>= 1) cnt += __shfl_xor_sync(0xFFFFFFFFu, cnt, o);
    if (lid == 0 && cnt) atomicAdd(&g_count, cnt);
}

// ============================================================================
// Kernel 2: finalize scalar
// ============================================================================
__global__ void fin_kernel(float* out) {
    out[0] = (float)((double)g_count * 100.0 / (double)NUM_GRAPHS);
}

// ============================================================================
extern "C" void kernel_launch(void* const* d_in, const int* in_sizes, int n_in,
                              void* d_out, int out_size) {
    const float* x   = (const float*)d_in[0];
    const int*   pos = (const int*)  d_in[1];
    const int*   neg = (const int*)  d_in[2];
    // d_in[3] = batch (irrelevant: mean of segment sums == total/512)
    const float* W1  = (const float*)d_in[4];
    const float* b1  = (const float*)d_in[5];
    const float* W2  = (const float*)d_in[6];
    const float* b2  = (const float*)d_in[7];

    int Ep = in_sizes[1] / 2;
    int En = in_sizes[2] / 2;
    int n4 = in_sizes[0] / 4;

    static int configured = 0;
    if (!configured) {
        cudaFuncSetAttribute(gae_main_kernel,
                             cudaFuncAttributeMaxDynamicSharedMemorySize,
                             SMEM_TOTAL);
        configured = 1;
    }

    int sms = 148;
    cudaDeviceGetAttribute(&sms, cudaDevAttrMultiProcessorCount, 0);
    if (sms <= 0) sms = 148;

    cvt_kernel<<<1024, 256>>>(x, n4);
    gae_main_kernel<<<sms, NTHREADS, SMEM_TOTAL>>>(pos, neg, W1, b1, W2, b2, Ep, En);
    fin_kernel<<<1, 1>>>((float*)d_out);
}

// round 7
// speedup vs baseline: 1.5368x; 1.5368x over previous
#include <cuda_runtime.h>
#include <cuda_bf16.h>
#include <cstdint>

// ============================================================================
// output = 100/512 * (#pos edges with logit<=0.5 + #neg edges with logit>0.5)
// logit = W2 . relu(W1 . relu(x_i*x_j) + b1) + b2.
// (mean of segment sums == total/NUM_GRAPHS, so `batch` is irrelevant;
//  each misclassified edge contributes exactly 100 to the total loss.)
//
// R7: TILE_M=256 (halves W1 ldmatrix re-read traffic), double-buffered A tile
// with the gather of tile t+1 software-pipelined INSIDE the MMA loop of tile t
// (per-warp-private edge indices, shfl broadcast, depth-2 LDG pipeline).
// ============================================================================

#define NUM_GRAPHS 512
#define HDIM 160
#define TILE_M 256
#define NTHREADS 256
#define ROWB 336              // padded row pitch (bytes): 84 words mod 32 banks -> conflict-free ldsm

// ---- scratch (no cudaMalloc allowed) ----
__device__ __nv_bfloat16 g_xbf[16000000];   // 100000 x 160 bf16 = 32MB
__device__ int g_count;

// ---- dynamic SMEM layout (bytes) ----
#define OFF_A0   0                          // 256 x 336 = 86016
#define OFF_A1   86016                      // 256 x 336 = 86016
#define OFF_B    172032                     // 160 x 336 = 53760
#define OFF_BW   225792                     // float2[160] {b1,w2} = 1280
#define SMEM_TOTAL 227072

__device__ __forceinline__ uint32_t smem_u32(const void* p) {
    uint32_t a;
    asm("{ .reg .u64 t; cvta.to.shared.u64 t, %1; cvt.u32.u64 %0, t; }"
        : "=r"(a) : "l"(p));
    return a;
}

__device__ __forceinline__ void ldsm_x4(uint32_t* r, uint32_t addr) {
    asm volatile("ldmatrix.sync.aligned.m8n8.x4.shared.b16 {%0,%1,%2,%3}, [%4];"
                 : "=r"(r[0]), "=r"(r[1]), "=r"(r[2]), "=r"(r[3]) : "r"(addr));
}

__device__ __forceinline__ void mma16816(float* d, const uint32_t* a,
                                         const uint32_t* b) {
    asm volatile(
        "mma.sync.aligned.m16n8k16.row.col.f32.bf16.bf16.f32 "
        "{%0,%1,%2,%3}, {%4,%5,%6,%7}, {%8,%9}, {%0,%1,%2,%3};"
        : "+f"(d[0]), "+f"(d[1]), "+f"(d[2]), "+f"(d[3])
        : "r"(a[0]), "r"(a[1]), "r"(a[2]), "r"(a[3]), "r"(b[0]), "r"(b[1]));
}

// bf16x2 multiply + relu, packed
__device__ __forceinline__ uint32_t bfmr(uint32_t a, uint32_t b) {
    __nv_bfloat162 x = *reinterpret_cast<__nv_bfloat162*>(&a);
    __nv_bfloat162 y = *reinterpret_cast<__nv_bfloat162*>(&b);
    __nv_bfloat162 z = __hmul2(x, y);
    const __nv_bfloat162 zero = __float2bfloat162_rn(0.0f);
    z = __hmax2(z, zero);
    return *reinterpret_cast<uint32_t*>(&z);
}

// gather addressing: per warp, 32 next-tile edges; lane groups of 4 read 64B
// contiguous per edge. it in [0,20): eo = edge-in-warp, ch = uint4 chunk.
#define G_EO(it) ((lid >> 2) + (((it) / 5) << 3))
#define G_CH(it) (((it) % 5) * 4 + (lid & 3))

#define GLOAD(it, VA, VB) do {                                   \
    int _eo = G_EO(it);                                          \
    int _ch = G_CH(it);                                          \
    int _ii = __shfl_sync(0xFFFFFFFFu, myI, _eo);                \
    int _jj = __shfl_sync(0xFFFFFFFFu, myJ, _eo);                \
    VA = xrows[(size_t)_ii * 20 + _ch];                          \
    VB = xrows[(size_t)_jj * 20 + _ch];                          \
} while (0)

#define GSTORE(it, VA, VB, DSTOFF) do {                          \
    int _eo = G_EO(it);                                          \
    int _ch = G_CH(it);                                          \
    uint4 _r;                                                    \
    _r.x = bfmr((VA).x, (VB).x);                                 \
    _r.y = bfmr((VA).y, (VB).y);                                 \
    _r.z = bfmr((VA).z, (VB).z);                                 \
    _r.w = bfmr((VA).w, (VB).w);                                 \
    *reinterpret_cast<uint4*>(smem + (DSTOFF) + _eo * ROWB + _ch * 16) = _r; \
} while (0)

// ============================================================================
// Kernel 0: convert x -> bf16 scratch, zero counter
// ============================================================================
__global__ void cvt_kernel(const float* __restrict__ x, int n4) {
    if (blockIdx.x == 0 && threadIdx.x == 0) g_count = 0;
    int stride = gridDim.x * blockDim.x;
    uint2* out = reinterpret_cast<uint2*>(g_xbf);
    const float4* in = reinterpret_cast<const float4*>(x);
    for (int i = blockIdx.x * blockDim.x + threadIdx.x; i < n4; i += stride) {
        float4 v = in[i];
        __nv_bfloat162 p0 = __floats2bfloat162_rn(v.x, v.y);
        __nv_bfloat162 p1 = __floats2bfloat162_rn(v.z, v.w);
        uint2 o;
        o.x = *reinterpret_cast<uint32_t*>(&p0);
        o.y = *reinterpret_cast<uint32_t*>(&p1);
        out[i] = o;
    }
}

// ============================================================================
// Kernel 1: persistent fused edge-MLP + misclassification count
// ============================================================================
__global__ void __launch_bounds__(NTHREADS, 1)
gae_main_kernel(const int* __restrict__ pos, const int* __restrict__ neg,
                const float* __restrict__ W1, const float* __restrict__ b1,
                const float* __restrict__ W2, const float* __restrict__ b2,
                int Ep, int En) {
    extern __shared__ char smem[];
    const uint32_t sb = smem_u32(smem);
    const int tid = threadIdx.x;
    const int wid = tid >> 5;
    const int lid = tid & 31;
    const int Etot = Ep + En;
    const int ntiles = (Etot + TILE_M - 1) / TILE_M;

    // --- load W1 -> SMEM B [160 rows x 336B pitch], f32 -> bf16 ---
    {
        const float4* w1v = reinterpret_cast<const float4*>(W1);
        #pragma unroll 5
        for (int it = 0; it < 25; ++it) {
            int idx = it * NTHREADS + tid;        // 0..6399
            int n  = idx / 40;                    // N row 0..159
            int kc = idx - n * 40;                // float4 chunk 0..39
            float4 w = w1v[idx];
            __nv_bfloat162 p0 = __floats2bfloat162_rn(w.x, w.y);
            __nv_bfloat162 p1 = __floats2bfloat162_rn(w.z, w.w);
            uint2 v;
            v.x = *reinterpret_cast<uint32_t*>(&p0);
            v.y = *reinterpret_cast<uint32_t*>(&p1);
            *reinterpret_cast<uint2*>(smem + OFF_B + n * ROWB + kc * 8) = v;
        }
    }
    if (tid < HDIM) {
        reinterpret_cast<float2*>(smem + OFF_BW)[tid] = make_float2(b1[tid], W2[tid]);
    }

    const float2* sbw = reinterpret_cast<const float2*>(smem + OFF_BW);
    const uint4* xrows = reinterpret_cast<const uint4*>(g_xbf);  // 20 uint4/row
    const float b2v = b2[0];

    // per-thread ldmatrix address components
    const uint32_t aoff = (uint32_t)((wid * 32 + ((lid >> 3) & 1) * 8 + (lid & 7)) * ROWB
                                     + (lid >> 4) * 16);
    const uint32_t bBase = sb + OFF_B
        + (uint32_t)((lid & 7) * ROWB) + (uint32_t)((lid >> 3) * 16);

    int cnt = 0;
    int tile = blockIdx.x;
    int buf = 0;                               // buffer holding CURRENT tile

    __syncthreads();                           // W1/BW ready

    if (tile < ntiles) {
        // ---- prologue: gather tile `tile` into buf0 ----
        {
            int g = tile * TILE_M + wid * 32 + lid;
            int myI = 0, myJ = 0;
            if (g < Etot) {
                if (g < Ep) { myI = pos[g];      myJ = pos[g + Ep]; }
                else        { int q = g - Ep; myI = neg[q]; myJ = neg[q + En]; }
            }
            const uint32_t dstOff = OFF_A0 + (uint32_t)(wid * 32 * ROWB);
            #pragma unroll 4
            for (int it = 0; it < 20; ++it) {
                uint4 va, vb;
                GLOAD(it, va, vb);
                GSTORE(it, va, vb, dstOff);
            }
        }
        __syncthreads();

        for (; tile < ntiles; tile += gridDim.x) {
            // ---- next-tile edge indices (register-resident, per warp slice) ----
            const int nt = tile + gridDim.x;
            const bool gat = (nt < ntiles);
            int myI = 0, myJ = 0;
            if (gat) {
                int g = nt * TILE_M + wid * 32 + lid;
                if (g < Etot) {
                    if (g < Ep) { myI = pos[g];      myJ = pos[g + Ep]; }
                    else        { int q = g - Ep; myI = neg[q]; myJ = neg[q + En]; }
                }
            }
            const uint32_t aBase = sb + (buf ? OFF_A1 : OFF_A0) + aoff;
            const uint32_t dstOff = (buf ? OFF_A0 : OFF_A1) + (uint32_t)(wid * 32 * ROWB);

            // ---- A fragments: this warp's 32 rows, all K (80 regs) ----
            uint32_t af[2][10][4];
            #pragma unroll
            for (int m = 0; m < 2; ++m)
                #pragma unroll
                for (int s = 0; s < 10; ++s)
                    ldsm_x4(af[m][s], aBase + (uint32_t)(m * 16 * ROWB + s * 32));

            // ---- depth-2 gather pipeline prefetch ----
            uint4 va[2], vb[2];
            if (gat) { GLOAD(0, va[0], vb[0]); GLOAD(1, va[1], vb[1]); }

            float acc[2][2] = {{0.0f, 0.0f}, {0.0f, 0.0f}};

            #pragma unroll 4
            for (int j = 0; j < 20; ++j) {
                float d0[4] = {0.0f, 0.0f, 0.0f, 0.0f};
                float d1[4] = {0.0f, 0.0f, 0.0f, 0.0f};
                const uint32_t bj = bBase + (uint32_t)(j * 8 * ROWB);
                #pragma unroll
                for (int s2 = 0; s2 < 5; ++s2) {
                    uint32_t br[4];
                    ldsm_x4(br, bj + (uint32_t)(s2 * 64));   // k-steps 2s2, 2s2+1
                    mma16816(d0, af[0][2 * s2],     br);
                    mma16816(d0, af[0][2 * s2 + 1], br + 2);
                    mma16816(d1, af[1][2 * s2],     br);
                    mma16816(d1, af[1][2 * s2 + 1], br + 2);
                }
                if (gat) {
                    GSTORE(j, va[j & 1], vb[j & 1], dstOff); // consume stage j
                    if (j + 2 < 20) GLOAD(j + 2, va[j & 1], vb[j & 1]);
                }
                const int n0 = j * 8 + (lid & 3) * 2;
                const float2 bw0 = sbw[n0];
                const float2 bw1 = sbw[n0 + 1];
                acc[0][0] += fmaxf(d0[0] + bw0.x, 0.0f) * bw0.y
                           + fmaxf(d0[1] + bw1.x, 0.0f) * bw1.y;
                acc[0][1] += fmaxf(d0[2] + bw0.x, 0.0f) * bw0.y
                           + fmaxf(d0[3] + bw1.x, 0.0f) * bw1.y;
                acc[1][0] += fmaxf(d1[0] + bw0.x, 0.0f) * bw0.y
                           + fmaxf(d1[1] + bw1.x, 0.0f) * bw1.y;
                acc[1][1] += fmaxf(d1[2] + bw0.x, 0.0f) * bw0.y
                           + fmaxf(d1[3] + bw1.x, 0.0f) * bw1.y;
            }

            // ---- reduce 4 lanes/row, threshold, count ----
            #pragma unroll
            for (int m = 0; m < 2; ++m) {
                #pragma unroll
                for (int h = 0; h < 2; ++h) {
                    float a = acc[m][h];
                    a += __shfl_xor_sync(0xFFFFFFFFu, a, 1);
                    a += __shfl_xor_sync(0xFFFFFFFFu, a, 2);
                    if ((lid & 3) == 0) {
                        int r = tile * TILE_M + wid * 32 + m * 16 + (lid >> 2) + h * 8;
                        if (r < Etot) {
                            bool pred = (a + b2v) > 0.5f;
                            if (pred != (r < Ep)) cnt++;
                        }
                    }
                }
            }
            buf ^= 1;
            __syncthreads();   // next-tile A fully written; current A consumed
        }
    }

    // ---- reduce counts ----
    #pragma unroll
    for (int o = 16; o; o >>= 1) cnt += __shfl_xor_sync(0xFFFFFFFFu, cnt, o);
    if (lid == 0 && cnt) atomicAdd(&g_count, cnt);
}

// ============================================================================
// Kernel 2: finalize scalar
// ============================================================================
__global__ void fin_kernel(float* out) {
    out[0] = (float)((double)g_count * 100.0 / (double)NUM_GRAPHS);
}

// ============================================================================
extern "C" void kernel_launch(void* const* d_in, const int* in_sizes, int n_in,
                              void* d_out, int out_size) {
    const float* x   = (const float*)d_in[0];
    const int*   pos = (const int*)  d_in[1];
    const int*   neg = (const int*)  d_in[2];
    // d_in[3] = batch (irrelevant: mean of segment sums == total/512)
    const float* W1  = (const float*)d_in[4];
    const float* b1  = (const float*)d_in[5];
    const float* W2  = (const float*)d_in[6];
    const float* b2  = (const float*)d_in[7];

    int Ep = in_sizes[1] / 2;
    int En = in_sizes[2] / 2;
    int n4 = in_sizes[0] / 4;

    static int configured = 0;
    if (!configured) {
        cudaFuncSetAttribute(gae_main_kernel,
                             cudaFuncAttributeMaxDynamicSharedMemorySize,
                             SMEM_TOTAL);
        configured = 1;
    }

    int sms = 148;
    cudaDeviceGetAttribute(&sms, cudaDevAttrMultiProcessorCount, 0);
    if (sms <= 0) sms = 148;

    cvt_kernel<<<1024, 256>>>(x, n4);
    gae_main_kernel<<<sms, NTHREADS, SMEM_TOTAL>>>(pos, neg, W1, b1, W2, b2, Ep, En);
    fin_kernel<<<1, 1>>>((float*)d_out);
}